// round 4
// baseline (speedup 1.0000x reference)
#include <cuda_runtime.h>
#include <cuda_bf16.h>
#include <math.h>

// IoU3DLoss: only the DIAGONAL of the reference's (m,m) IoU matrix is used,
// so this is an O(m) elementwise 3D-IoU + (-log) mean reduction.
//
// Single block, single launch: 1024 threads, grid-stride over m=4096 rows,
// warp-shuffle + shared-memory block reduction, thread 0 writes the scalar.

#define OFFSET_C 1e-6f
#define EPS_C    1e-6f

__global__ __launch_bounds__(1024, 1)
void iou3d_loss_kernel(const float* __restrict__ pred,
                       const float* __restrict__ target,
                       float* __restrict__ out, int m)
{
    float lsum = 0.0f;   // sum of -log(iou) over valid rows
    float cnt  = 0.0f;   // number of valid rows

    for (int i = threadIdx.x; i < m; i += blockDim.x) {
        const float* p = pred   + 7 * i;
        const float* t = target + 7 * i;

        float px = p[0], py = p[1], pz = p[2];
        float pw = p[3], pl = p[4], ph = p[5], pr = p[6];
        float tx = t[0], ty = t[1], tz = t[2];
        float tw = t[3], tl = t[4], th = t[5], tr = t[6];

        // Axis-aligned BEV extents of the rotated rectangle.
        // Corners are {±A±B}; max over the 4 corners equals |A|+|B|
        // bitwise-identically to the reference's explicit min/max.
        float pc, ps; sincosf(pr, &ps, &pc);
        float tc, ts; sincosf(tr, &ts, &tc);

        float pex = fabsf((0.5f * pw) * pc) + fabsf((0.5f * pl) * ps);
        float pey = fabsf((0.5f * pw) * ps) + fabsf((0.5f * pl) * pc);
        float tex = fabsf((0.5f * tw) * tc) + fabsf((0.5f * tl) * ts);
        float tey = fabsf((0.5f * tw) * ts) + fabsf((0.5f * tl) * tc);

        float pxmin = px - pex, pxmax = px + pex;
        float pymin = py - pey, pymax = py + pey;
        float txmin = tx - tex, txmax = tx + tex;
        float tymin = ty - tey, tymax = ty + tey;

        // BEV overlap (with +offset before clamp, per reference)
        float wx = fmaxf(fminf(pxmax, txmax) - fmaxf(pxmin, txmin) + OFFSET_C, 0.0f);
        float wy = fmaxf(fminf(pymax, tymax) - fmaxf(pymin, tymin) + OFFSET_C, 0.0f);
        float overlap_bev = wx * wy;

        // Height overlap: z is box top, [z-h, z]
        float oh = fmaxf(fminf(pz, tz) - fmaxf(pz - ph, tz - th), 0.0f);

        float o3   = overlap_bev * oh;
        float pvol = pw * pl * ph;
        float tvol = tw * tl * th;
        float denom = fmaxf(pvol + tvol - o3, EPS_C);
        float iou3d = fminf(fmaxf(o3 / denom, EPS_C), 1.0f);

        bool valid = (pw > 0.0f) && (pl > 0.0f) && (ph > 0.0f);
        if (valid) {
            lsum += -logf(iou3d);
            cnt  += 1.0f;
        }
    }

    // Warp reduction
    #pragma unroll
    for (int off = 16; off > 0; off >>= 1) {
        lsum += __shfl_down_sync(0xFFFFFFFFu, lsum, off);
        cnt  += __shfl_down_sync(0xFFFFFFFFu, cnt,  off);
    }

    __shared__ float s_sum[32];
    __shared__ float s_cnt[32];
    int lane = threadIdx.x & 31;
    int wid  = threadIdx.x >> 5;
    if (lane == 0) { s_sum[wid] = lsum; s_cnt[wid] = cnt; }
    __syncthreads();

    if (wid == 0) {
        int nwarps = (blockDim.x + 31) >> 5;
        float v = (lane < nwarps) ? s_sum[lane] : 0.0f;
        float c = (lane < nwarps) ? s_cnt[lane] : 0.0f;
        #pragma unroll
        for (int off = 16; off > 0; off >>= 1) {
            v += __shfl_down_sync(0xFFFFFFFFu, v, off);
            c += __shfl_down_sync(0xFFFFFFFFu, c, off);
        }
        if (lane == 0) {
            out[0] = (c > 0.0f) ? (v / fmaxf(c, 1.0f)) : 0.0f;
        }
    }
}

extern "C" void kernel_launch(void* const* d_in, const int* in_sizes, int n_in,
                              void* d_out, int out_size)
{
    const float* pred   = (const float*)d_in[0];
    const float* target = (const float*)d_in[1];
    float* out = (float*)d_out;
    int m = in_sizes[0] / 7;

    iou3d_loss_kernel<<<1, 1024>>>(pred, target, out, m);
}

// round 5
// speedup vs baseline: 1.2399x; 1.2399x over previous
#include <cuda_runtime.h>
#include <cuda_bf16.h>
#include <math.h>

// IoU3DLoss: diagonal-only 3D IoU + (-log) mean. O(m) work, m=4096.
//
// 32 blocks x 128 threads = 4096 threads, 1 row/thread, one wave across 32 SMs.
// Each block writes a deterministic partial (sum, cnt) to a __device__ scratch
// array; the last-arriving block (atomic counter) reduces the 32 partials and
// writes the scalar, then resets the counter for the next graph replay.

#define OFFSET_C 1e-6f
#define EPS_C    1e-6f

#define NBLK 32
#define NTHR 128

__device__ float    g_part_sum[NBLK];
__device__ float    g_part_cnt[NBLK];
__device__ unsigned g_arrive = 0;

__device__ __forceinline__ float ld_cv(const float* p) {
    float v;
    asm volatile("ld.global.cv.f32 %0, [%1];" : "=f"(v) : "l"(p));
    return v;
}

__global__ __launch_bounds__(NTHR, 1)
void iou3d_loss_kernel(const float* __restrict__ pred,
                       const float* __restrict__ target,
                       float* __restrict__ out, int m)
{
    float lsum = 0.0f;
    float cnt  = 0.0f;

    const int stride = gridDim.x * blockDim.x;
    for (int i = blockIdx.x * blockDim.x + threadIdx.x; i < m; i += stride) {
        const float* p = pred   + 7 * i;
        const float* t = target + 7 * i;

        // 14 independent scalar loads -> front-batched by ptxas (MLP ~14)
        float px = p[0], py = p[1], pz = p[2];
        float pw = p[3], pl = p[4], ph = p[5], pr = p[6];
        float tx = t[0], ty = t[1], tz = t[2];
        float tw = t[3], tl = t[4], th = t[5], tr = t[6];

        // Axis-aligned extents of rotated BEV rectangle: corners {±A±B},
        // max = |A|+|B| bitwise-identical to explicit 4-corner min/max.
        float pc, ps; sincosf(pr, &ps, &pc);
        float tc, ts; sincosf(tr, &ts, &tc);

        float pex = fabsf((0.5f * pw) * pc) + fabsf((0.5f * pl) * ps);
        float pey = fabsf((0.5f * pw) * ps) + fabsf((0.5f * pl) * pc);
        float tex = fabsf((0.5f * tw) * tc) + fabsf((0.5f * tl) * ts);
        float tey = fabsf((0.5f * tw) * ts) + fabsf((0.5f * tl) * tc);

        // BEV overlap (+offset before clamp, per reference)
        float wx = fmaxf(fminf(px + pex, tx + tex) - fmaxf(px - pex, tx - tex) + OFFSET_C, 0.0f);
        float wy = fmaxf(fminf(py + pey, ty + tey) - fmaxf(py - pey, ty - tey) + OFFSET_C, 0.0f);
        float overlap_bev = wx * wy;

        // Height overlap: z is box top, interval [z-h, z]
        float oh = fmaxf(fminf(pz, tz) - fmaxf(pz - ph, tz - th), 0.0f);

        float o3    = overlap_bev * oh;
        float pvol  = pw * pl * ph;
        float tvol  = tw * tl * th;
        float denom = fmaxf(pvol + tvol - o3, EPS_C);
        float iou3d = fminf(fmaxf(o3 / denom, EPS_C), 1.0f);

        if ((pw > 0.0f) && (pl > 0.0f) && (ph > 0.0f)) {
            lsum += -logf(iou3d);
            cnt  += 1.0f;
        }
    }

    // ---- block reduction (4 warps) ----
    #pragma unroll
    for (int off = 16; off > 0; off >>= 1) {
        lsum += __shfl_down_sync(0xFFFFFFFFu, lsum, off);
        cnt  += __shfl_down_sync(0xFFFFFFFFu, cnt,  off);
    }

    __shared__ float s_sum[4];
    __shared__ float s_cnt[4];
    int lane = threadIdx.x & 31;
    int wid  = threadIdx.x >> 5;
    if (lane == 0) { s_sum[wid] = lsum; s_cnt[wid] = cnt; }
    __syncthreads();

    if (threadIdx.x == 0) {
        float bs = s_sum[0] + s_sum[1] + s_sum[2] + s_sum[3];
        float bc = s_cnt[0] + s_cnt[1] + s_cnt[2] + s_cnt[3];

        g_part_sum[blockIdx.x] = bs;
        g_part_cnt[blockIdx.x] = bc;
        __threadfence();  // release partials before arrival

        unsigned old = atomicAdd(&g_arrive, 1u);
        if (old == gridDim.x - 1) {
            // Last block: all partials are globally visible.
            __threadfence();
            float tsum = 0.0f, tcnt = 0.0f;
            #pragma unroll
            for (int b = 0; b < NBLK; b++) {
                tsum += ld_cv(&g_part_sum[b]);
                tcnt += ld_cv(&g_part_cnt[b]);
            }
            out[0] = (tcnt > 0.0f) ? (tsum / fmaxf(tcnt, 1.0f)) : 0.0f;
            atomicExch(&g_arrive, 0u);  // reset for next graph replay
        }
    }
}

extern "C" void kernel_launch(void* const* d_in, const int* in_sizes, int n_in,
                              void* d_out, int out_size)
{
    const float* pred   = (const float*)d_in[0];
    const float* target = (const float*)d_in[1];
    float* out = (float*)d_out;
    int m = in_sizes[0] / 7;

    iou3d_loss_kernel<<<NBLK, NTHR>>>(pred, target, out, m);
}